// round 1
// baseline (speedup 1.0000x reference)
#include <cuda_runtime.h>
#include <cuda_bf16.h>

// Problem constants (fixed by the reference)
#define NN 50000
#define EE 800000
#define HH 64
#define EDD 32
#define LL 3
#define GG 256
#define OUTD 32
#define EDGE_CAT 10
#define SCALE 0.125f  // 1/sqrt(64)

// ---------------- scratch (device globals; no allocation allowed) -----------
__device__ float d_h[NN * HH];
__device__ float d_q[NN * HH];
__device__ float d_k[NN * HH];
__device__ float d_v[NN * HH];
__device__ float d_s[NN * HH];      // skip projection h@Wskip + bskip
__device__ float d_agg[NN * HH];
__device__ float d_alpha[EE];
__device__ unsigned d_nmax[NN];
__device__ float d_ndenom[NN];
__device__ float d_ecat[EDGE_CAT * HH];
__device__ float d_gate[NN];
__device__ unsigned d_gmax[GG];
__device__ float d_gdenom[GG];

// order-preserving float<->uint encoding for atomicMax on floats
#define ENC_NEG_INF 0x007fffffu
__device__ __forceinline__ unsigned enc_f(float f) {
    unsigned b = __float_as_uint(f);
    return (b & 0x80000000u) ? ~b : (b | 0x80000000u);
}
__device__ __forceinline__ float dec_f(unsigned u) {
    unsigned b = (u & 0x80000000u) ? (u & 0x7fffffffu) : ~u;
    return __uint_as_float(b);
}

// ---------------- kernels ---------------------------------------------------

__global__ void embed_kernel(const int* __restrict__ x,
                             const float* __restrict__ node_emb) {
    int i = blockIdx.x * blockDim.x + threadIdx.x;
    if (i < NN * HH) {
        int n = i >> 6, j = i & 63;
        d_h[i] = node_emb[x[n] * HH + j];
    }
}

__global__ void init_layer_kernel() {
    int i = blockIdx.x * blockDim.x + threadIdx.x;
    if (i < NN * HH) d_agg[i] = 0.f;
    if (i < NN) {
        d_nmax[i] = ENC_NEG_INF;
        d_ndenom[i] = 0.f;
    }
}

// e_cat[cat][j] = sum_c edge_emb[cat][c] * We[c][j]   (10 x 64)
__global__ void ecat_kernel(const float* __restrict__ edge_emb,
                            const float* __restrict__ We) {
    int cat = blockIdx.x, j = threadIdx.x;
    float acc = 0.f;
#pragma unroll
    for (int c = 0; c < EDD; c++)
        acc += edge_emb[cat * EDD + c] * We[c * HH + j];
    d_ecat[cat * HH + j] = acc;
}

// q,k,v,skip projections. 16 nodes per 256-thread block; thread = (group g, out j)
__global__ void qkvs_kernel(const float* __restrict__ Wq, const float* __restrict__ Wk,
                            const float* __restrict__ Wv, const float* __restrict__ Ws,
                            const float* __restrict__ bq, const float* __restrict__ bk,
                            const float* __restrict__ bv, const float* __restrict__ bs) {
    __shared__ float hs[16][HH];
    int j = threadIdx.x & 63;
    int g = threadIdx.x >> 6;  // 0..3
    int base = blockIdx.x * 16;
    for (int r = g; r < 16; r += 4) {
        int n = base + r;
        hs[r][j] = (n < NN) ? d_h[n * HH + j] : 0.f;
    }
    __syncthreads();
    float aq[4] = {0, 0, 0, 0}, ak[4] = {0, 0, 0, 0};
    float av[4] = {0, 0, 0, 0}, as_[4] = {0, 0, 0, 0};
    for (int c = 0; c < HH; c++) {
        float wq = Wq[c * HH + j], wk = Wk[c * HH + j];
        float wv = Wv[c * HH + j], ws = Ws[c * HH + j];
#pragma unroll
        for (int r = 0; r < 4; r++) {
            float hv = hs[g + r * 4][c];
            aq[r] += hv * wq; ak[r] += hv * wk;
            av[r] += hv * wv; as_[r] += hv * ws;
        }
    }
    float bqj = bq[j], bkj = bk[j], bvj = bv[j], bsj = bs[j];
#pragma unroll
    for (int r = 0; r < 4; r++) {
        int n = base + g + r * 4;
        if (n < NN) {
            d_q[n * HH + j] = aq[r] + bqj;
            d_k[n * HH + j] = ak[r] + bkj;
            d_v[n * HH + j] = av[r] + bvj;
            d_s[n * HH + j] = as_[r] + bsj;
        }
    }
}

// alpha[e] = dot(q[dst], k[src] + ecat[attr]) * SCALE; atomicMax per dst
// 8 lanes per edge
__global__ void alpha_kernel(const int* __restrict__ src, const int* __restrict__ dst,
                             const int* __restrict__ ea) {
    int gid = blockIdx.x * blockDim.x + threadIdx.x;
    int e = gid >> 3, lane = gid & 7;
    if (e >= EE) return;
    int s = src[e], d = dst[e], c = ea[e];
    const float4* q4 = (const float4*)(d_q + (size_t)d * HH);
    const float4* k4 = (const float4*)(d_k + (size_t)s * HH);
    const float4* e4 = (const float4*)(d_ecat + c * HH);
    float acc = 0.f;
#pragma unroll
    for (int u = 0; u < 2; u++) {
        int idx = lane * 2 + u;
        float4 qa = q4[idx], ka = k4[idx], eb = e4[idx];
        acc += qa.x * (ka.x + eb.x) + qa.y * (ka.y + eb.y) +
               qa.z * (ka.z + eb.z) + qa.w * (ka.w + eb.w);
    }
    acc += __shfl_xor_sync(0xffffffffu, acc, 1);
    acc += __shfl_xor_sync(0xffffffffu, acc, 2);
    acc += __shfl_xor_sync(0xffffffffu, acc, 4);
    if (lane == 0) {
        float a = acc * SCALE;
        d_alpha[e] = a;
        atomicMax(&d_nmax[d], enc_f(a));
    }
}

__global__ void expd_kernel(const int* __restrict__ dst) {
    int e = blockIdx.x * blockDim.x + threadIdx.x;
    if (e >= EE) return;
    int d = dst[e];
    float ex = __expf(d_alpha[e] - dec_f(d_nmax[d]));
    d_alpha[e] = ex;
    atomicAdd(&d_ndenom[d], ex);
}

// agg[dst] += (v[src] + ecat[attr]) * (exp/denom); 8 lanes/edge, float4 atomics
__global__ void agg_kernel(const int* __restrict__ src, const int* __restrict__ dst,
                           const int* __restrict__ ea) {
    int gid = blockIdx.x * blockDim.x + threadIdx.x;
    int e = gid >> 3, lane = gid & 7;
    if (e >= EE) return;
    int s = src[e], d = dst[e], c = ea[e];
    float coeff = d_alpha[e] / d_ndenom[d];
    const float4* v4 = (const float4*)(d_v + (size_t)s * HH);
    const float4* e4 = (const float4*)(d_ecat + c * HH);
    float4* a4 = (float4*)(d_agg + (size_t)d * HH);
#pragma unroll
    for (int u = 0; u < 2; u++) {
        int idx = lane * 2 + u;
        float4 vv = v4[idx], eb = e4[idx];
        float4 m;
        m.x = (vv.x + eb.x) * coeff;
        m.y = (vv.y + eb.y) * coeff;
        m.z = (vv.z + eb.z) * coeff;
        m.w = (vv.w + eb.w) * coeff;
        atomicAdd(&a4[idx], m);
    }
}

__global__ void relu_kernel() {
    int i = blockIdx.x * blockDim.x + threadIdx.x;
    if (i < NN * HH) d_h[i] = fmaxf(d_agg[i] + d_s[i], 0.f);
}

__global__ void readout_init_kernel(float* __restrict__ out) {
    int i = blockIdx.x * blockDim.x + threadIdx.x;
    if (i < GG * OUTD) out[i] = 0.f;
    if (i < GG) {
        d_gmax[i] = ENC_NEG_INF;
        d_gdenom[i] = 0.f;
    }
}

// gate[n] = h[n] . gate_W + gate_b; atomicMax per graph. 8 lanes/node.
__global__ void gate_kernel(const int* __restrict__ batch,
                            const float* __restrict__ gate_W,
                            const float* __restrict__ gate_b) {
    int gid = blockIdx.x * blockDim.x + threadIdx.x;
    int n = gid >> 3, lane = gid & 7;
    if (n >= NN) return;
    const float4* h4 = (const float4*)(d_h + (size_t)n * HH);
    const float4* w4 = (const float4*)gate_W;
    float acc = 0.f;
#pragma unroll
    for (int u = 0; u < 2; u++) {
        int idx = lane * 2 + u;
        float4 hv = h4[idx], wv = w4[idx];
        acc += hv.x * wv.x + hv.y * wv.y + hv.z * wv.z + hv.w * wv.w;
    }
    acc += __shfl_xor_sync(0xffffffffu, acc, 1);
    acc += __shfl_xor_sync(0xffffffffu, acc, 2);
    acc += __shfl_xor_sync(0xffffffffu, acc, 4);
    if (lane == 0) {
        float gv = acc + gate_b[0];
        d_gate[n] = gv;
        atomicMax(&d_gmax[batch[n]], enc_f(gv));
    }
}

__global__ void gexp_kernel(const int* __restrict__ batch) {
    int n = blockIdx.x * blockDim.x + threadIdx.x;
    if (n >= NN) return;
    int b = batch[n];
    float g = __expf(d_gate[n] - dec_f(d_gmax[b]));
    d_gate[n] = g;
    atomicAdd(&d_gdenom[b], g);
}

// out[batch[n]] += (gate/denom) * (h[n] @ out_W + out_b); 8 nodes/block
__global__ void out_kernel(const int* __restrict__ batch,
                           const float* __restrict__ out_W,
                           const float* __restrict__ out_b,
                           float* __restrict__ out) {
    __shared__ float ow[HH * OUTD];   // 8KB
    __shared__ float hs[8][HH];
    int t = threadIdx.x;
    for (int i = t; i < HH * OUTD; i += 256) ow[i] = out_W[i];
    for (int i = t; i < 8 * HH; i += 256) {
        int r = i >> 6, c = i & 63;
        int n2 = blockIdx.x * 8 + r;
        hs[r][c] = (n2 < NN) ? d_h[n2 * HH + c] : 0.f;
    }
    __syncthreads();
    int j = t & 31, g = t >> 5;   // output dim / node group
    int n = blockIdx.x * 8 + g;
    if (n >= NN) return;
    float acc = out_b[j];
#pragma unroll
    for (int c = 0; c < HH; c++) acc += hs[g][c] * ow[c * OUTD + j];
    int b = batch[n];
    float w = d_gate[n] / d_gdenom[b];
    atomicAdd(&out[b * OUTD + j], w * acc);
}

// ---------------- launch -----------------------------------------------------

extern "C" void kernel_launch(void* const* d_in, const int* in_sizes, int n_in,
                              void* d_out, int out_size) {
    const int* x          = (const int*)d_in[0];
    const int* edge_index = (const int*)d_in[1];
    const int* src        = edge_index;
    const int* dst        = edge_index + EE;
    const int* ea         = (const int*)d_in[2];
    const int* batch      = (const int*)d_in[3];
    const float* node_emb = (const float*)d_in[4];
    const float* edge_emb = (const float*)d_in[5];
    const float* Wq       = (const float*)d_in[6];
    const float* Wk       = (const float*)d_in[7];
    const float* Wv       = (const float*)d_in[8];
    const float* We       = (const float*)d_in[9];
    const float* Wskip    = (const float*)d_in[10];
    const float* bq       = (const float*)d_in[11];
    const float* bk       = (const float*)d_in[12];
    const float* bv       = (const float*)d_in[13];
    const float* bskip    = (const float*)d_in[14];
    const float* gate_W   = (const float*)d_in[15];
    const float* gate_b   = (const float*)d_in[16];
    const float* out_W    = (const float*)d_in[17];
    const float* out_b    = (const float*)d_in[18];
    float* out            = (float*)d_out;

    const int NH_BLOCKS = (NN * HH + 255) / 256;
    const int E8_BLOCKS = (EE * 8 + 255) / 256;
    const int E_BLOCKS  = (EE + 255) / 256;

    embed_kernel<<<NH_BLOCKS, 256>>>(x, node_emb);

    for (int l = 0; l < LL; l++) {
        init_layer_kernel<<<NH_BLOCKS, 256>>>();
        ecat_kernel<<<EDGE_CAT, HH>>>(edge_emb, We + (size_t)l * EDD * HH);
        qkvs_kernel<<<(NN + 15) / 16, 256>>>(
            Wq + (size_t)l * HH * HH, Wk + (size_t)l * HH * HH,
            Wv + (size_t)l * HH * HH, Wskip + (size_t)l * HH * HH,
            bq + (size_t)l * HH, bk + (size_t)l * HH,
            bv + (size_t)l * HH, bskip + (size_t)l * HH);
        alpha_kernel<<<E8_BLOCKS, 256>>>(src, dst, ea);
        expd_kernel<<<E_BLOCKS, 256>>>(dst);
        agg_kernel<<<E8_BLOCKS, 256>>>(src, dst, ea);
        relu_kernel<<<NH_BLOCKS, 256>>>();
    }

    readout_init_kernel<<<(GG * OUTD + 255) / 256, 256>>>(out);
    gate_kernel<<<(NN * 8 + 255) / 256, 256>>>(batch, gate_W, gate_b);
    gexp_kernel<<<(NN + 255) / 256, 256>>>(batch);
    out_kernel<<<(NN + 7) / 8, 256>>>(batch, out_W, out_b, out);
}

// round 2
// speedup vs baseline: 1.3374x; 1.3374x over previous
#include <cuda_runtime.h>
#include <cuda_bf16.h>

// Problem constants (fixed by the reference)
#define NN 50000
#define EE 800000
#define HH 64
#define EDD 32
#define LL 3
#define GG 256
#define OUTD 32
#define EDGE_CAT 10
#define SCALE 0.125f  // 1/sqrt(64)

// ---------------- scratch (device globals; no allocation allowed) -----------
__device__ float d_h[NN * HH];
__device__ float d_q[NN * HH];
__device__ float d_k[NN * HH];
__device__ float d_v[NN * HH];
__device__ float d_s[NN * HH];      // skip projection h@Wskip + bskip
__device__ float d_ecat[LL * EDGE_CAT * HH];
__device__ float d_gate[NN];
__device__ unsigned d_gmax[GG];
__device__ float d_gdenom[GG];
// CSR scratch
__device__ int d_deg[NN];
__device__ int d_rowptr[NN + 1];
__device__ int d_wp[NN];
__device__ int d_csr[EE];           // packed: src | (cat<<16)

// order-preserving float<->uint encoding for atomicMax on floats
#define ENC_NEG_INF 0x007fffffu
__device__ __forceinline__ unsigned enc_f(float f) {
    unsigned b = __float_as_uint(f);
    return (b & 0x80000000u) ? ~b : (b | 0x80000000u);
}
__device__ __forceinline__ float dec_f(unsigned u) {
    unsigned b = (u & 0x80000000u) ? (u & 0x7fffffffu) : ~u;
    return __uint_as_float(b);
}

// ---------------- CSR build --------------------------------------------------

__global__ void hist_init_kernel() {
    int i = blockIdx.x * blockDim.x + threadIdx.x;
    if (i < NN) d_deg[i] = 0;
}

__global__ void hist_kernel(const int* __restrict__ dst) {
    int e = blockIdx.x * blockDim.x + threadIdx.x;
    if (e < EE) atomicAdd(&d_deg[dst[e]], 1);
}

// single-block exclusive scan of d_deg -> d_rowptr (and d_wp copy)
__global__ void scan_kernel() {
    __shared__ int wsum[32];
    __shared__ int carry_s;
    int t = threadIdx.x, lane = t & 31, w = t >> 5;
    if (t == 0) carry_s = 0;
    __syncthreads();
    for (int base = 0; base < NN; base += 1024) {
        int i = base + t;
        int v = (i < NN) ? d_deg[i] : 0;
        int x = v;
#pragma unroll
        for (int o = 1; o < 32; o <<= 1) {
            int y = __shfl_up_sync(0xffffffffu, x, o);
            if (lane >= o) x += y;
        }
        if (lane == 31) wsum[w] = x;
        __syncthreads();
        if (w == 0) {
            int ws = wsum[lane];
#pragma unroll
            for (int o = 1; o < 32; o <<= 1) {
                int y = __shfl_up_sync(0xffffffffu, ws, o);
                if (lane >= o) ws += y;
            }
            wsum[lane] = ws;
        }
        __syncthreads();
        int incl = x + (w > 0 ? wsum[w - 1] : 0) + carry_s;
        if (i < NN) {
            d_rowptr[i] = incl - v;
            d_wp[i] = incl - v;
        }
        __syncthreads();
        if (t == 1023) carry_s = incl;
        __syncthreads();
    }
    if (t == 0) d_rowptr[NN] = carry_s;
}

__global__ void scatter_kernel(const int* __restrict__ src,
                               const int* __restrict__ dst,
                               const int* __restrict__ ea) {
    int e = blockIdx.x * blockDim.x + threadIdx.x;
    if (e >= EE) return;
    int d = dst[e];
    int pos = atomicAdd(&d_wp[d], 1);
    d_csr[pos] = src[e] | (ea[e] << 16);
}

// ---------------- misc small kernels -----------------------------------------

__global__ void embed_kernel(const int* __restrict__ x,
                             const float* __restrict__ node_emb) {
    int i = blockIdx.x * blockDim.x + threadIdx.x;
    if (i < NN * HH) {
        int n = i >> 6, j = i & 63;
        d_h[i] = node_emb[x[n] * HH + j];
    }
}

// e_cat[l][cat][j] = sum_c edge_emb[cat][c] * We[l][c][j]   for all layers
__global__ void ecat_kernel(const float* __restrict__ edge_emb,
                            const float* __restrict__ We) {
    int l = blockIdx.x / EDGE_CAT;
    int cat = blockIdx.x % EDGE_CAT;
    int j = threadIdx.x;
    const float* W = We + (size_t)l * EDD * HH;
    float acc = 0.f;
#pragma unroll
    for (int c = 0; c < EDD; c++)
        acc += edge_emb[cat * EDD + c] * W[c * HH + j];
    d_ecat[(l * EDGE_CAT + cat) * HH + j] = acc;
}

// q,k,v,skip projections. 16 nodes per 256-thread block
__global__ void qkvs_kernel(const float* __restrict__ Wq, const float* __restrict__ Wk,
                            const float* __restrict__ Wv, const float* __restrict__ Ws,
                            const float* __restrict__ bq, const float* __restrict__ bk,
                            const float* __restrict__ bv, const float* __restrict__ bs) {
    __shared__ float hs[16][HH];
    int j = threadIdx.x & 63;
    int g = threadIdx.x >> 6;  // 0..3
    int base = blockIdx.x * 16;
    for (int r = g; r < 16; r += 4) {
        int n = base + r;
        hs[r][j] = (n < NN) ? d_h[n * HH + j] : 0.f;
    }
    __syncthreads();
    float aq[4] = {0, 0, 0, 0}, ak[4] = {0, 0, 0, 0};
    float av[4] = {0, 0, 0, 0}, as_[4] = {0, 0, 0, 0};
    for (int c = 0; c < HH; c++) {
        float wq = Wq[c * HH + j], wk = Wk[c * HH + j];
        float wv = Wv[c * HH + j], ws = Ws[c * HH + j];
#pragma unroll
        for (int r = 0; r < 4; r++) {
            float hv = hs[g + r * 4][c];
            aq[r] += hv * wq; ak[r] += hv * wk;
            av[r] += hv * wv; as_[r] += hv * ws;
        }
    }
    float bqj = bq[j], bkj = bk[j], bvj = bv[j], bsj = bs[j];
#pragma unroll
    for (int r = 0; r < 4; r++) {
        int n = base + g + r * 4;
        if (n < NN) {
            d_q[n * HH + j] = aq[r] + bqj;
            d_k[n * HH + j] = ak[r] + bkj;
            d_v[n * HH + j] = av[r] + bvj;
            d_s[n * HH + j] = as_[r] + bsj;
        }
    }
}

// ---------------- fused flash-style attention layer ---------------------------
// one warp per dst node; online softmax over its in-edges; writes relu(agg+skip)
__global__ void attn_kernel(int layer) {
    __shared__ float ec_s[EDGE_CAT * HH];
    const float* ec = d_ecat + layer * EDGE_CAT * HH;
    for (int i = threadIdx.x; i < EDGE_CAT * HH; i += blockDim.x)
        ec_s[i] = ec[i];
    __syncthreads();

    int warp = (blockIdx.x * blockDim.x + threadIdx.x) >> 5;
    int lane = threadIdx.x & 31;
    if (warp >= NN) return;
    int n = warp;
    int beg = d_rowptr[n], end = d_rowptr[n + 1];

    float2 q = *(const float2*)(d_q + (size_t)n * HH + 2 * lane);
    float m = -1e30f, ssum = 0.f;
    float2 acc = make_float2(0.f, 0.f);

    for (int p = beg; p < end; p++) {
        int packed = d_csr[p];
        int s = packed & 0xffff;
        int cat = packed >> 16;
        float2 e = *(const float2*)(ec_s + cat * HH + 2 * lane);
        float2 k = *(const float2*)(d_k + (size_t)s * HH + 2 * lane);
        float2 v = *(const float2*)(d_v + (size_t)s * HH + 2 * lane);
        float part = q.x * (k.x + e.x) + q.y * (k.y + e.y);
        part += __shfl_xor_sync(0xffffffffu, part, 1);
        part += __shfl_xor_sync(0xffffffffu, part, 2);
        part += __shfl_xor_sync(0xffffffffu, part, 4);
        part += __shfl_xor_sync(0xffffffffu, part, 8);
        part += __shfl_xor_sync(0xffffffffu, part, 16);
        float alpha = part * SCALE;
        float mn = fmaxf(m, alpha);
        float c = __expf(m - mn);
        float pw = __expf(alpha - mn);
        ssum = ssum * c + pw;
        acc.x = acc.x * c + pw * (v.x + e.x);
        acc.y = acc.y * c + pw * (v.y + e.y);
        m = mn;
    }
    float inv = (ssum > 0.f) ? (1.f / ssum) : 0.f;
    float2 sk = *(const float2*)(d_s + (size_t)n * HH + 2 * lane);
    float2 h;
    h.x = fmaxf(acc.x * inv + sk.x, 0.f);
    h.y = fmaxf(acc.y * inv + sk.y, 0.f);
    *(float2*)(d_h + (size_t)n * HH + 2 * lane) = h;
}

// ---------------- readout -----------------------------------------------------

__global__ void readout_init_kernel(float* __restrict__ out) {
    int i = blockIdx.x * blockDim.x + threadIdx.x;
    if (i < GG * OUTD) out[i] = 0.f;
    if (i < GG) {
        d_gmax[i] = ENC_NEG_INF;
        d_gdenom[i] = 0.f;
    }
}

// gate[n] = h[n] . gate_W + gate_b; atomicMax per graph. 8 lanes/node.
__global__ void gate_kernel(const int* __restrict__ batch,
                            const float* __restrict__ gate_W,
                            const float* __restrict__ gate_b) {
    int gid = blockIdx.x * blockDim.x + threadIdx.x;
    int n = gid >> 3, lane = gid & 7;
    if (n >= NN) return;
    const float4* h4 = (const float4*)(d_h + (size_t)n * HH);
    const float4* w4 = (const float4*)gate_W;
    float acc = 0.f;
#pragma unroll
    for (int u = 0; u < 2; u++) {
        int idx = lane * 2 + u;
        float4 hv = h4[idx], wv = w4[idx];
        acc += hv.x * wv.x + hv.y * wv.y + hv.z * wv.z + hv.w * wv.w;
    }
    acc += __shfl_xor_sync(0xffffffffu, acc, 1);
    acc += __shfl_xor_sync(0xffffffffu, acc, 2);
    acc += __shfl_xor_sync(0xffffffffu, acc, 4);
    if (lane == 0) {
        float gv = acc + gate_b[0];
        d_gate[n] = gv;
        atomicMax(&d_gmax[batch[n]], enc_f(gv));
    }
}

__global__ void gexp_kernel(const int* __restrict__ batch) {
    int n = blockIdx.x * blockDim.x + threadIdx.x;
    if (n >= NN) return;
    int b = batch[n];
    float g = __expf(d_gate[n] - dec_f(d_gmax[b]));
    d_gate[n] = g;
    atomicAdd(&d_gdenom[b], g);
}

// out[batch[n]] += (gate/denom) * (h[n] @ out_W + out_b); 8 nodes/block
__global__ void out_kernel(const int* __restrict__ batch,
                           const float* __restrict__ out_W,
                           const float* __restrict__ out_b,
                           float* __restrict__ out) {
    __shared__ float ow[HH * OUTD];   // 8KB
    __shared__ float hs[8][HH];
    int t = threadIdx.x;
    for (int i = t; i < HH * OUTD; i += 256) ow[i] = out_W[i];
    for (int i = t; i < 8 * HH; i += 256) {
        int r = i >> 6, c = i & 63;
        int n2 = blockIdx.x * 8 + r;
        hs[r][c] = (n2 < NN) ? d_h[n2 * HH + c] : 0.f;
    }
    __syncthreads();
    int j = t & 31, g = t >> 5;
    int n = blockIdx.x * 8 + g;
    if (n >= NN) return;
    float acc = out_b[j];
#pragma unroll
    for (int c = 0; c < HH; c++) acc += hs[g][c] * ow[c * OUTD + j];
    int b = batch[n];
    float w = d_gate[n] / d_gdenom[b];
    atomicAdd(&out[b * OUTD + j], w * acc);
}

// ---------------- launch -----------------------------------------------------

extern "C" void kernel_launch(void* const* d_in, const int* in_sizes, int n_in,
                              void* d_out, int out_size) {
    const int* x          = (const int*)d_in[0];
    const int* edge_index = (const int*)d_in[1];
    const int* src        = edge_index;
    const int* dst        = edge_index + EE;
    const int* ea         = (const int*)d_in[2];
    const int* batch      = (const int*)d_in[3];
    const float* node_emb = (const float*)d_in[4];
    const float* edge_emb = (const float*)d_in[5];
    const float* Wq       = (const float*)d_in[6];
    const float* Wk       = (const float*)d_in[7];
    const float* Wv       = (const float*)d_in[8];
    const float* We       = (const float*)d_in[9];
    const float* Wskip    = (const float*)d_in[10];
    const float* bq       = (const float*)d_in[11];
    const float* bk       = (const float*)d_in[12];
    const float* bv       = (const float*)d_in[13];
    const float* bskip    = (const float*)d_in[14];
    const float* gate_W   = (const float*)d_in[15];
    const float* gate_b   = (const float*)d_in[16];
    const float* out_W    = (const float*)d_in[17];
    const float* out_b    = (const float*)d_in[18];
    float* out            = (float*)d_out;

    const int NH_BLOCKS = (NN * HH + 255) / 256;
    const int E_BLOCKS  = (EE + 255) / 256;
    const int N_BLOCKS  = (NN + 255) / 256;

    // CSR build (by dst)
    hist_init_kernel<<<N_BLOCKS, 256>>>();
    hist_kernel<<<E_BLOCKS, 256>>>(dst);
    scan_kernel<<<1, 1024>>>();
    scatter_kernel<<<E_BLOCKS, 256>>>(src, dst, ea);

    embed_kernel<<<NH_BLOCKS, 256>>>(x, node_emb);
    ecat_kernel<<<LL * EDGE_CAT, HH>>>(edge_emb, We);

    for (int l = 0; l < LL; l++) {
        qkvs_kernel<<<(NN + 15) / 16, 256>>>(
            Wq + (size_t)l * HH * HH, Wk + (size_t)l * HH * HH,
            Wv + (size_t)l * HH * HH, Wskip + (size_t)l * HH * HH,
            bq + (size_t)l * HH, bk + (size_t)l * HH,
            bv + (size_t)l * HH, bskip + (size_t)l * HH);
        attn_kernel<<<(NN * 32 + 255) / 256, 256>>>(l);
    }

    readout_init_kernel<<<(GG * OUTD + 255) / 256, 256>>>(out);
    gate_kernel<<<(NN * 8 + 255) / 256, 256>>>(batch, gate_W, gate_b);
    gexp_kernel<<<N_BLOCKS, 256>>>(batch);
    out_kernel<<<(NN + 7) / 8, 256>>>(batch, out_W, out_b, out);
}

// round 4
// speedup vs baseline: 1.4561x; 1.0887x over previous
#include <cuda_runtime.h>
#include <cuda_bf16.h>

// Problem constants (fixed by the reference)
#define NN 50000
#define EE 800000
#define HH 64
#define EDD 32
#define LL 3
#define GG 256
#define OUTD 32
#define EDGE_CAT 10
#define SCALE 0.125f  // 1/sqrt(64)

// ---------------- scratch (device globals; no allocation allowed) -----------
__device__ float d_h[NN * HH];
__device__ float d_q[NN * HH];
__device__ float d_k[NN * HH];
__device__ float d_v[NN * HH];
__device__ float d_s[NN * HH];      // skip projection h@Wskip + bskip
__device__ float d_ecat[LL * EDGE_CAT * HH];
__device__ float d_gate[NN];
__device__ unsigned d_gmax[GG];
__device__ float d_gdenom[GG];
// CSR scratch
__device__ int d_deg[NN];
__device__ int d_rowptr[NN + 1];
__device__ int d_wp[NN];
__device__ int d_csr[EE];           // packed: src | (cat<<16)

// order-preserving float<->uint encoding for atomicMax on floats
#define ENC_NEG_INF 0x007fffffu
__device__ __forceinline__ unsigned enc_f(float f) {
    unsigned b = __float_as_uint(f);
    return (b & 0x80000000u) ? ~b : (b | 0x80000000u);
}
__device__ __forceinline__ float dec_f(unsigned u) {
    unsigned b = (u & 0x80000000u) ? (u & 0x7fffffffu) : ~u;
    return __uint_as_float(b);
}

// ---------------- CSR build --------------------------------------------------

__global__ void hist_init_kernel() {
    int i = blockIdx.x * blockDim.x + threadIdx.x;
    if (i < NN) d_deg[i] = 0;
}

__global__ void hist_kernel(const int* __restrict__ dst) {
    int e = blockIdx.x * blockDim.x + threadIdx.x;
    if (e < EE) atomicAdd(&d_deg[dst[e]], 1);
}

// single-block exclusive scan of d_deg -> d_rowptr (and d_wp copy)
__global__ void scan_kernel() {
    __shared__ int wsum[32];
    __shared__ int carry_s;
    int t = threadIdx.x, lane = t & 31, w = t >> 5;
    if (t == 0) carry_s = 0;
    __syncthreads();
    for (int base = 0; base < NN; base += 1024) {
        int i = base + t;
        int v = (i < NN) ? d_deg[i] : 0;
        int x = v;
#pragma unroll
        for (int o = 1; o < 32; o <<= 1) {
            int y = __shfl_up_sync(0xffffffffu, x, o);
            if (lane >= o) x += y;
        }
        if (lane == 31) wsum[w] = x;
        __syncthreads();
        if (w == 0) {
            int ws = wsum[lane];
#pragma unroll
            for (int o = 1; o < 32; o <<= 1) {
                int y = __shfl_up_sync(0xffffffffu, ws, o);
                if (lane >= o) ws += y;
            }
            wsum[lane] = ws;
        }
        __syncthreads();
        int incl = x + (w > 0 ? wsum[w - 1] : 0) + carry_s;
        if (i < NN) {
            d_rowptr[i] = incl - v;
            d_wp[i] = incl - v;
        }
        __syncthreads();
        if (t == 1023) carry_s = incl;
        __syncthreads();
    }
    if (t == 0) d_rowptr[NN] = carry_s;
}

__global__ void scatter_kernel(const int* __restrict__ src,
                               const int* __restrict__ dst,
                               const int* __restrict__ ea) {
    int e = blockIdx.x * blockDim.x + threadIdx.x;
    if (e >= EE) return;
    int d = dst[e];
    int pos = atomicAdd(&d_wp[d], 1);
    d_csr[pos] = src[e] | (ea[e] << 16);
}

// ---------------- misc small kernels -----------------------------------------

// e_cat[l][cat][j] = sum_c edge_emb[cat][c] * We[l][c][j]   for all layers
__global__ void ecat_kernel(const float* __restrict__ edge_emb,
                            const float* __restrict__ We) {
    int l = blockIdx.x / EDGE_CAT;
    int cat = blockIdx.x % EDGE_CAT;
    int j = threadIdx.x;
    const float* W = We + (size_t)l * EDD * HH;
    float acc = 0.f;
#pragma unroll
    for (int c = 0; c < EDD; c++)
        acc += edge_emb[cat * EDD + c] * W[c * HH + j];
    d_ecat[(l * EDGE_CAT + cat) * HH + j] = acc;
}

// ---------------- register-tiled projection GEMM ------------------------------
// One 64x64 weight matrix per blockIdx.y (0:q 1:k 2:v 3:skip).
// BM=128 nodes, BK=64 (full). 256 threads, 8x4 register tile each.
// Static smem: h-tile transposed [64][128] (32KB) + W [64][64] (16KB) = 48KB.
__global__ void __launch_bounds__(256, 2)
proj_gemm(const float* __restrict__ Wq, const float* __restrict__ Wk,
          const float* __restrict__ Wv, const float* __restrict__ Ws,
          const float* __restrict__ bq, const float* __restrict__ bk,
          const float* __restrict__ bv, const float* __restrict__ bs,
          const int* __restrict__ x, const float* __restrict__ node_emb,
          int layer0) {
    __shared__ float hs_t[64 * 128];
    __shared__ float ws[64 * 64];

    const float* W;
    const float* bias;
    float* out;
    switch (blockIdx.y) {
        case 0:  W = Wq; bias = bq; out = d_q; break;
        case 1:  W = Wk; bias = bk; out = d_k; break;
        case 2:  W = Wv; bias = bv; out = d_v; break;
        default: W = Ws; bias = bs; out = d_s; break;
    }

    int t = threadIdx.x;
    int nodeBase = blockIdx.x * 128;

    // h tile load + transpose: thread t covers half a node row (8 float4)
    {
        int n = t >> 1;                 // 0..127
        int half = (t & 1) * 8;        // float4 offset within row
        int gn = nodeBase + n;
        const float* hrow = nullptr;
        if (gn < NN)
            hrow = layer0 ? (node_emb + (size_t)x[gn] * HH)
                          : (d_h + (size_t)gn * HH);
#pragma unroll
        for (int i = 0; i < 8; i++) {
            int c4 = half + i;
            float4 hv = make_float4(0.f, 0.f, 0.f, 0.f);
            if (hrow) hv = *(const float4*)(hrow + c4 * 4);
            int c = c4 * 4;
            hs_t[(c + 0) * 128 + n] = hv.x;
            hs_t[(c + 1) * 128 + n] = hv.y;
            hs_t[(c + 2) * 128 + n] = hv.z;
            hs_t[(c + 3) * 128 + n] = hv.w;
        }
    }
    // weight load: 4096 floats = 1024 float4, 4 per thread
#pragma unroll
    for (int i = 0; i < 4; i++) {
        int fidx = t * 4 + i;
        *(float4*)(ws + fidx * 4) = *(const float4*)(W + fidx * 4);
    }
    __syncthreads();

    int tx = t >> 4;      // node group (8 nodes)
    int ty = t & 15;      // col group (4 cols)
    float acc[8][4];
#pragma unroll
    for (int u = 0; u < 8; u++)
#pragma unroll
        for (int w = 0; w < 4; w++) acc[u][w] = 0.f;

#pragma unroll 4
    for (int c = 0; c < 64; c++) {
        float4 a0 = *(const float4*)(hs_t + c * 128 + tx * 8);
        float4 a1 = *(const float4*)(hs_t + c * 128 + tx * 8 + 4);
        float4 b  = *(const float4*)(ws + c * 64 + ty * 4);
        float a[8] = {a0.x, a0.y, a0.z, a0.w, a1.x, a1.y, a1.z, a1.w};
        float bv4[4] = {b.x, b.y, b.z, b.w};
#pragma unroll
        for (int u = 0; u < 8; u++)
#pragma unroll
            for (int w = 0; w < 4; w++)
                acc[u][w] += a[u] * bv4[w];
    }

    float4 bb = *(const float4*)(bias + ty * 4);
#pragma unroll
    for (int u = 0; u < 8; u++) {
        int n = nodeBase + tx * 8 + u;
        if (n < NN) {
            float4 o = make_float4(acc[u][0] + bb.x, acc[u][1] + bb.y,
                                   acc[u][2] + bb.z, acc[u][3] + bb.w);
            *(float4*)(out + (size_t)n * HH + ty * 4) = o;
        }
    }
}

// ---------------- fused flash-style attention layer ---------------------------
// one warp per dst node; pairwise online softmax over its in-edges;
// writes relu(agg + skip) into d_h
__global__ void attn_kernel(int layer) {
    __shared__ float ec_s[EDGE_CAT * HH];
    const float* ec = d_ecat + layer * EDGE_CAT * HH;
    for (int i = threadIdx.x; i < EDGE_CAT * HH; i += blockDim.x)
        ec_s[i] = ec[i];
    __syncthreads();

    int warp = (blockIdx.x * blockDim.x + threadIdx.x) >> 5;
    int lane = threadIdx.x & 31;
    if (warp >= NN) return;
    int n = warp;
    int beg = d_rowptr[n], end = d_rowptr[n + 1];

    float2 q = *(const float2*)(d_q + (size_t)n * HH + 2 * lane);
    float m = -1e30f, ssum = 0.f;
    float2 acc = make_float2(0.f, 0.f);

    int p = beg;
    for (; p + 1 < end; p += 2) {
        int packed0 = d_csr[p];
        int packed1 = d_csr[p + 1];
        int s0 = packed0 & 0xffff, cat0 = packed0 >> 16;
        int s1 = packed1 & 0xffff, cat1 = packed1 >> 16;
        float2 e0 = *(const float2*)(ec_s + cat0 * HH + 2 * lane);
        float2 k0 = *(const float2*)(d_k + (size_t)s0 * HH + 2 * lane);
        float2 v0 = *(const float2*)(d_v + (size_t)s0 * HH + 2 * lane);
        float2 e1 = *(const float2*)(ec_s + cat1 * HH + 2 * lane);
        float2 k1 = *(const float2*)(d_k + (size_t)s1 * HH + 2 * lane);
        float2 v1 = *(const float2*)(d_v + (size_t)s1 * HH + 2 * lane);
        float p0 = q.x * (k0.x + e0.x) + q.y * (k0.y + e0.y);
        float p1 = q.x * (k1.x + e1.x) + q.y * (k1.y + e1.y);
#pragma unroll
        for (int o = 1; o < 32; o <<= 1) {
            p0 += __shfl_xor_sync(0xffffffffu, p0, o);
            p1 += __shfl_xor_sync(0xffffffffu, p1, o);
        }
        float a0 = p0 * SCALE, a1 = p1 * SCALE;
        float mn = fmaxf(m, fmaxf(a0, a1));
        float c = __expf(m - mn);
        float w0 = __expf(a0 - mn);
        float w1 = __expf(a1 - mn);
        ssum = ssum * c + w0 + w1;
        acc.x = acc.x * c + w0 * (v0.x + e0.x) + w1 * (v1.x + e1.x);
        acc.y = acc.y * c + w0 * (v0.y + e0.y) + w1 * (v1.y + e1.y);
        m = mn;
    }
    if (p < end) {
        int packed = d_csr[p];
        int s = packed & 0xffff, cat = packed >> 16;
        float2 e = *(const float2*)(ec_s + cat * HH + 2 * lane);
        float2 k = *(const float2*)(d_k + (size_t)s * HH + 2 * lane);
        float2 v = *(const float2*)(d_v + (size_t)s * HH + 2 * lane);
        float part = q.x * (k.x + e.x) + q.y * (k.y + e.y);
#pragma unroll
        for (int o = 1; o < 32; o <<= 1)
            part += __shfl_xor_sync(0xffffffffu, part, o);
        float alpha = part * SCALE;
        float mn = fmaxf(m, alpha);
        float c = __expf(m - mn);
        float pw = __expf(alpha - mn);
        ssum = ssum * c + pw;
        acc.x = acc.x * c + pw * (v.x + e.x);
        acc.y = acc.y * c + pw * (v.y + e.y);
        m = mn;
    }
    float inv = (ssum > 0.f) ? (1.f / ssum) : 0.f;
    float2 sk = *(const float2*)(d_s + (size_t)n * HH + 2 * lane);
    float2 h;
    h.x = fmaxf(acc.x * inv + sk.x, 0.f);
    h.y = fmaxf(acc.y * inv + sk.y, 0.f);
    *(float2*)(d_h + (size_t)n * HH + 2 * lane) = h;
}

// ---------------- readout -----------------------------------------------------

__global__ void readout_init_kernel(float* __restrict__ out) {
    int i = blockIdx.x * blockDim.x + threadIdx.x;
    if (i < GG * OUTD) out[i] = 0.f;
    if (i < GG) {
        d_gmax[i] = ENC_NEG_INF;
        d_gdenom[i] = 0.f;
    }
}

// gate[n] = h[n] . gate_W + gate_b; atomicMax per graph. 8 lanes/node.
__global__ void gate_kernel(const int* __restrict__ batch,
                            const float* __restrict__ gate_W,
                            const float* __restrict__ gate_b) {
    int gid = blockIdx.x * blockDim.x + threadIdx.x;
    int n = gid >> 3, lane = gid & 7;
    if (n >= NN) return;
    const float4* h4 = (const float4*)(d_h + (size_t)n * HH);
    const float4* w4 = (const float4*)gate_W;
    float acc = 0.f;
#pragma unroll
    for (int u = 0; u < 2; u++) {
        int idx = lane * 2 + u;
        float4 hv = h4[idx], wv = w4[idx];
        acc += hv.x * wv.x + hv.y * wv.y + hv.z * wv.z + hv.w * wv.w;
    }
    acc += __shfl_xor_sync(0xffffffffu, acc, 1);
    acc += __shfl_xor_sync(0xffffffffu, acc, 2);
    acc += __shfl_xor_sync(0xffffffffu, acc, 4);
    if (lane == 0) {
        float gv = acc + gate_b[0];
        d_gate[n] = gv;
        atomicMax(&d_gmax[batch[n]], enc_f(gv));
    }
}

__global__ void gexp_kernel(const int* __restrict__ batch) {
    int n = blockIdx.x * blockDim.x + threadIdx.x;
    if (n >= NN) return;
    int b = batch[n];
    float g = __expf(d_gate[n] - dec_f(d_gmax[b]));
    d_gate[n] = g;
    atomicAdd(&d_gdenom[b], g);
}

// out[batch[n]] += (gate/denom) * (h[n] @ out_W + out_b); 8 nodes/block
__global__ void out_kernel(const int* __restrict__ batch,
                           const float* __restrict__ out_W,
                           const float* __restrict__ out_b,
                           float* __restrict__ out) {
    __shared__ float ow[HH * OUTD];   // 8KB
    __shared__ float hs[8][HH];
    int t = threadIdx.x;
    for (int i = t; i < HH * OUTD; i += 256) ow[i] = out_W[i];
    for (int i = t; i < 8 * HH; i += 256) {
        int r = i >> 6, c = i & 63;
        int n2 = blockIdx.x * 8 + r;
        hs[r][c] = (n2 < NN) ? d_h[n2 * HH + c] : 0.f;
    }
    __syncthreads();
    int j = t & 31, g = t >> 5;
    int n = blockIdx.x * 8 + g;
    if (n >= NN) return;
    float acc = out_b[j];
#pragma unroll
    for (int c = 0; c < HH; c++) acc += hs[g][c] * ow[c * OUTD + j];
    int b = batch[n];
    float w = d_gate[n] / d_gdenom[b];
    atomicAdd(&out[b * OUTD + j], w * acc);
}

// ---------------- launch -----------------------------------------------------

extern "C" void kernel_launch(void* const* d_in, const int* in_sizes, int n_in,
                              void* d_out, int out_size) {
    const int* x          = (const int*)d_in[0];
    const int* edge_index = (const int*)d_in[1];
    const int* src        = edge_index;
    const int* dst        = edge_index + EE;
    const int* ea         = (const int*)d_in[2];
    const int* batch      = (const int*)d_in[3];
    const float* node_emb = (const float*)d_in[4];
    const float* edge_emb = (const float*)d_in[5];
    const float* Wq       = (const float*)d_in[6];
    const float* Wk       = (const float*)d_in[7];
    const float* Wv       = (const float*)d_in[8];
    const float* We       = (const float*)d_in[9];
    const float* Wskip    = (const float*)d_in[10];
    const float* bq       = (const float*)d_in[11];
    const float* bk       = (const float*)d_in[12];
    const float* bv       = (const float*)d_in[13];
    const float* bskip    = (const float*)d_in[14];
    const float* gate_W   = (const float*)d_in[15];
    const float* gate_b   = (const float*)d_in[16];
    const float* out_W    = (const float*)d_in[17];
    const float* out_b    = (const float*)d_in[18];
    float* out            = (float*)d_out;

    const int E_BLOCKS  = (EE + 255) / 256;
    const int N_BLOCKS  = (NN + 255) / 256;

    // CSR build (by dst)
    hist_init_kernel<<<N_BLOCKS, 256>>>();
    hist_kernel<<<E_BLOCKS, 256>>>(dst);
    scan_kernel<<<1, 1024>>>();
    scatter_kernel<<<E_BLOCKS, 256>>>(src, dst, ea);

    ecat_kernel<<<LL * EDGE_CAT, HH>>>(edge_emb, We);

    dim3 gemm_grid((NN + 127) / 128, 4);
    for (int l = 0; l < LL; l++) {
        proj_gemm<<<gemm_grid, 256>>>(
            Wq + (size_t)l * HH * HH, Wk + (size_t)l * HH * HH,
            Wv + (size_t)l * HH * HH, Wskip + (size_t)l * HH * HH,
            bq + (size_t)l * HH, bk + (size_t)l * HH,
            bv + (size_t)l * HH, bskip + (size_t)l * HH,
            x, node_emb, (l == 0) ? 1 : 0);
        attn_kernel<<<(NN * 32 + 255) / 256, 256>>>(l);
    }

    readout_init_kernel<<<(GG * OUTD + 255) / 256, 256>>>(out);
    gate_kernel<<<(NN * 8 + 255) / 256, 256>>>(batch, gate_W, gate_b);
    gexp_kernel<<<N_BLOCKS, 256>>>(batch);
    out_kernel<<<(NN + 7) / 8, 256>>>(batch, out_W, out_b, out);
}